// round 13
// baseline (speedup 1.0000x reference)
#include <cuda_runtime.h>
#include <math.h>
#include <stdint.h>

#define NGRAPH 32
#define NNODE  1024
#define CDIM   64
#define KTOP   16
#define NROWS  (NGRAPH * NNODE)            // 32768
#define OUT_ELEMS (NROWS * CDIM)           // 2097152
#define ROWS_OFF  OUT_ELEMS
#define COLS_OFF  (OUT_ELEMS + NROWS * KTOP)

__device__ float g_sq[NROWS];

// ---------------------------------------------------------------------------
// Encoder + fused row squared-norms.  4x4 register tile, 64-row blocks.
// ---------------------------------------------------------------------------
#define ENC_WT   0
#define ENC_X    8448
#define ENC_TOTF 16640
#define ENC_BYTES (ENC_TOTF * 4)

__global__ void __launch_bounds__(256) enc_kernel(const float* __restrict__ x,
                                                  const float* __restrict__ W,
                                                  const float* __restrict__ b,
                                                  float* __restrict__ out) {
    extern __shared__ float esm[];
    float* sWt = esm + ENC_WT;
    float* sX  = esm + ENC_X;
    int tid = threadIdx.x;
    int i0 = blockIdx.x * 64;

    for (int idx = tid; idx < 128 * 64; idx += 256) {
        int k = idx >> 6, c = idx & 63;
        sWt[c * 132 + k] = W[idx];
    }
    for (int idx = tid; idx < 64 * 128 / 4; idx += 256) {
        ((float4*)sX)[idx] = ((const float4*)(x + (size_t)i0 * 128))[idx];
    }
    __syncthreads();

    int cgrp = tid & 15;
    int rgrp = tid >> 4;
    float acc[4][4];
#pragma unroll
    for (int rr = 0; rr < 4; rr++)
#pragma unroll
        for (int cc = 0; cc < 4; cc++) acc[rr][cc] = 0.f;

#pragma unroll
    for (int k4 = 0; k4 < 32; k4++) {
        float4 wv[4];
#pragma unroll
        for (int cc = 0; cc < 4; cc++)
            wv[cc] = *(const float4*)(sWt + (cgrp + 16 * cc) * 132 + k4 * 4);
#pragma unroll
        for (int rr = 0; rr < 4; rr++) {
            float4 xv = *(const float4*)(sX + (rgrp * 4 + rr) * 128 + k4 * 4);
#pragma unroll
            for (int cc = 0; cc < 4; cc++) {
                acc[rr][cc] += xv.x * wv[cc].x + xv.y * wv[cc].y
                             + xv.z * wv[cc].z + xv.w * wv[cc].w;
            }
        }
    }

    float bb[4];
#pragma unroll
    for (int cc = 0; cc < 4; cc++) bb[cc] = b[cgrp + 16 * cc];

    float sqp[4] = {0.f, 0.f, 0.f, 0.f};
#pragma unroll
    for (int rr = 0; rr < 4; rr++) {
        int r = i0 + rgrp * 4 + rr;
#pragma unroll
        for (int cc = 0; cc < 4; cc++) {
            float val = acc[rr][cc] + bb[cc];
            out[(size_t)r * 64 + cgrp + 16 * cc] = val;
            sqp[rr] += val * val;
        }
    }
#pragma unroll
    for (int rr = 0; rr < 4; rr++) {
#pragma unroll
        for (int o = 8; o; o >>= 1) sqp[rr] += __shfl_xor_sync(0xffffffffu, sqp[rr], o);
    }
    if (cgrp == 0) {
#pragma unroll
        for (int rr = 0; rr < 4; rr++) g_sq[i0 + rgrp * 4 + rr] = sqp[rr];
    }
}

// ---------------------------------------------------------------------------
// JAX threefry2x32, key (0,1), partitionable counter mode (verified R3).
// ---------------------------------------------------------------------------
__device__ __forceinline__ uint32_t threefry_bits_k01(uint32_t e) {
    const uint32_t ks0 = 0u, ks1 = 1u, ks2 = 0x1BD11BDBu;
    uint32_t x0 = 0u + ks0;
    uint32_t x1 = e + ks1;
#define TF_ROUND(r) { x0 += x1; x1 = __funnelshift_l(x1, x1, (r)); x1 ^= x0; }
    TF_ROUND(13) TF_ROUND(15) TF_ROUND(26) TF_ROUND(6)
    x0 += ks1; x1 += ks2 + 1u;
    TF_ROUND(17) TF_ROUND(29) TF_ROUND(16) TF_ROUND(24)
    x0 += ks2; x1 += ks0 + 2u;
    TF_ROUND(13) TF_ROUND(15) TF_ROUND(26) TF_ROUND(6)
    x0 += ks0; x1 += ks1 + 3u;
    TF_ROUND(17) TF_ROUND(29) TF_ROUND(16) TF_ROUND(24)
    x0 += ks1; x1 += ks2 + 4u;
    TF_ROUND(13) TF_ROUND(15) TF_ROUND(26) TF_ROUND(6)
    x0 += ks2; x1 += ks0 + 5u;
#undef TF_ROUND
    return x0 ^ x1;
}

// Packed dual-FMA (sm_103a f32x2 pipe)
__device__ __forceinline__ void ffma2(unsigned long long& d,
                                      unsigned long long a,
                                      unsigned long long b) {
    asm("fma.rn.f32x2 %0, %1, %2, %0;" : "+l"(d) : "l"(a), "l"(b));
}

// ---------------------------------------------------------------------------
// Lazy-GEMM fused kernel: hash-only main loop + candidate flush on demand.
// Block = (graph g, 32-row i-strip), 256 threads, grid (32, 32).
// Warp ty owns rows ty*4..ty*4+3; candidate lists warp-private; NO block
// barriers in the main loop.
// ---------------------------------------------------------------------------
#define TI 32
#define FLUSH 24
#define CAP 56        // max after one step: 23 + 32 = 55
#define THR0 2.8f     // P(any row final 16th < 2.8) ~ 6e-5
#define LGMAX 1.001f  // rigorous upper bound on exp(-T*d)

__device__ __forceinline__ uint32_t cut_bits_from_thr(float thr) {
    float fcut = __expf(-__expf(-(thr - LGMAX))) - 2e-7f;
    return __float_as_uint(1.0f + fcut) & 0x007fffffu;
}

// Warp-collective flush of one row's candidate list: exact v = lg + gum,
// merge survivors into sorted top-16 in append (ascending-j) order.
__device__ __forceinline__ void flush_row(
    int gr,                 // global row (gbase + i0 + r)
    int gbase, int c, int tx, float nT,
    const float* __restrict__ h,
    const uint32_t* candMr, const int* candJr,
    float* tv, int* ti)
{
    const ulonglong2* Arow = (const ulonglong2*)(h + (size_t)gr * 64);
    float sqi = g_sq[gr];
    for (int base = 0; base < c; base += 32) {
        int idx = base + tx;
        bool act = idx < c;
        uint32_t mant = act ? candMr[idx] : 0u;
        int jg = act ? candJr[idx] : 0;
        float f   = __uint_as_float(mant | 0x3f800000u) - 1.0f;
        float gum = -__logf(-log1pf(f - 1.0f));     // -inf for inactive lanes
        const ulonglong2* Brow = (const ulonglong2*)(h + (size_t)(gbase + jg) * 64);
        unsigned long long a0 = 0ull;
#pragma unroll
        for (int k4 = 0; k4 < 16; k4++) {
            ulonglong2 av = Arow[k4];   // warp-uniform LDG (L1-hot)
            ulonglong2 bv = Brow[k4];   // divergent LDG (L2-hot)
            ffma2(a0, av.x, bv.x);
            ffma2(a0, av.y, bv.y);
        }
        float dot = __uint_as_float((uint32_t)a0)
                  + __uint_as_float((uint32_t)(a0 >> 32));
        float sqj = g_sq[gbase + jg];
        float s  = __fadd_rn(sqi, sqj);
        float d  = __fadd_rn(s, -__fmul_rn(2.0f, dot));
        float lg = __expf(__fmul_rn(nT, d));
        float v  = lg + gum;

        float t15 = tv[KTOP - 1];
        unsigned m = __ballot_sync(0xffffffffu, act && v > t15);
        while (m) {
            int src = __ffs(m) - 1; m &= m - 1;
            float vv = __shfl_sync(0xffffffffu, v, src);
            int   jj = __shfl_sync(0xffffffffu, jg, src);
            if (tx == 0 && vv > tv[KTOP - 1]) {
                int p = KTOP - 1;
                while (p > 0 && tv[p - 1] < vv) {
                    tv[p] = tv[p - 1]; ti[p] = ti[p - 1]; p--;
                }
                tv[p] = vv; ti[p] = jj;
            }
            __syncwarp();
        }
    }
}

__global__ void __launch_bounds__(256, 5) dgm_kernel(float* __restrict__ buf,
                                                     const float* __restrict__ tptr) {
    __shared__ uint32_t candM[TI][CAP];
    __shared__ int      candJ[TI][CAP];
    __shared__ float    topV[TI][KTOP];
    __shared__ int      topI[TI][KTOP];

    const float* h = buf;
    int tid = threadIdx.x;
    int tx  = tid & 31;
    int ty  = tid >> 5;
    int g   = blockIdx.x;
    int i0  = blockIdx.y * TI;
    int gbase = g * NNODE;
    int r0  = ty * 4;

    // warp-private init (no block sync needed)
    if (tx < KTOP) {
#pragma unroll
        for (int ii = 0; ii < 4; ii++) {
            topV[r0 + ii][tx] = -INFINITY;
            topI[r0 + ii][tx] = 0;
        }
    }
    __syncwarp();

    float nT = -(*tptr);
    uint32_t cut0 = cut_bits_from_thr(THR0);
    uint32_t cutM[4] = {cut0, cut0, cut0, cut0};
    int cn[4] = {0, 0, 0, 0};
    unsigned lanelt = (1u << tx) - 1u;

    for (int j0 = 0; j0 < NNODE; j0 += 32) {
        int jg = j0 + tx;
        uint32_t e0 = ((uint32_t)g << 20) + ((uint32_t)(i0 + r0) << 10) + (uint32_t)jg;
        uint32_t bts[4];
#pragma unroll
        for (int ii = 0; ii < 4; ii++)
            bts[ii] = threefry_bits_k01(e0 + ((uint32_t)ii << 10));
#pragma unroll
        for (int ii = 0; ii < 4; ii++) {
            uint32_t mant = bts[ii] >> 9;
            bool pass = mant > cutM[ii];
            unsigned msk = __ballot_sync(0xffffffffu, pass);
            if (msk) {
                int pos = cn[ii] + __popc(msk & lanelt);
                if (pass) {
                    candM[r0 + ii][pos] = mant;
                    candJ[r0 + ii][pos] = jg;
                }
                cn[ii] += __popc(msk);
            }
        }
        if ((cn[0] >= FLUSH) | (cn[1] >= FLUSH) | (cn[2] >= FLUSH) | (cn[3] >= FLUSH)) {
#pragma unroll
            for (int ii = 0; ii < 4; ii++) {
                if (cn[ii] >= FLUSH) {
                    int r = r0 + ii;
                    flush_row(gbase + i0 + r, gbase, cn[ii], tx, nT, h,
                              candM[r], candJ[r], topV[r], topI[r]);
                    cn[ii] = 0;
                    float nthr = fmaxf(topV[r][KTOP - 1], THR0);
                    cutM[ii] = cut_bits_from_thr(nthr);
                }
            }
        }
    }

    // final flush of remaining candidates
#pragma unroll
    for (int ii = 0; ii < 4; ii++) {
        if (cn[ii] > 0) {
            int r = r0 + ii;
            flush_row(gbase + i0 + r, gbase, cn[ii], tx, nT, h,
                      candM[r], candJ[r], topV[r], topI[r]);
        }
    }

    __syncthreads();   // all warps' topI final before cross-warp read

    // ---- write edges (indices as float) ----
    if (tid < TI) {
        int grow = gbase + i0 + tid;
        size_t base = (size_t)grow * KTOP;
        float rowv = (float)grow;
#pragma unroll
        for (int k = 0; k < KTOP; k++) {
            buf[ROWS_OFF + base + k] = rowv;
            buf[COLS_OFF + base + k] = (float)(gbase + topI[tid][k]);
        }
    }
}

// ---------------------------------------------------------------------------
extern "C" void kernel_launch(void* const* d_in, const int* in_sizes, int n_in,
                              void* d_out, int out_size) {
    const float* x    = (const float*)d_in[0];
    const float* W    = (const float*)d_in[1];
    const float* b    = (const float*)d_in[2];
    const float* temp = (const float*)d_in[3];
    float* out = (float*)d_out;

    cudaFuncSetAttribute(enc_kernel, cudaFuncAttributeMaxDynamicSharedMemorySize, ENC_BYTES);
    enc_kernel<<<NROWS / 64, 256, ENC_BYTES>>>(x, W, b, out);
    dgm_kernel<<<dim3(NGRAPH, NNODE / TI), 256>>>(out, temp);
}